// round 14
// baseline (speedup 1.0000x reference)
#include <cuda_runtime.h>
#include <cuda_fp16.h>
#include <math.h>
#include <stdint.h>

#define N_TOK 16384
#define DIM 768
#define NEXP 8
#define HID 2048
#define CAP 5120
#define ECAP (NEXP*CAP)
#define NP (N_TOK*2)
#define NCH 2048

// ---------------- device scratch ----------------
__device__ int   g_pair_expert[NP];
__device__ float g_pair_weight[NP];
__device__ int   g_pair_slot[NP];
__device__ int   g_slot_token[ECAP];
__device__ int   g_count[NEXP];
__device__ int   g_ch_cnt[NCH][NEXP];
__device__ int   g_ch_base[NCH][NEXP];
__device__ __half g_w13h[(size_t)NEXP*2*HID*DIM];
__device__ __half g_w2h [(size_t)NEXP*DIM*HID];
__device__ __half g_zbuf[(size_t)ECAP*DIM];
__device__ __half g_hbuf[(size_t)ECAP*HID];
__device__ __half g_ybuf[(size_t)ECAP*DIM];

// ---------------- helpers ----------------
__device__ __forceinline__ uint32_t smem_u32(const void* p) {
    return (uint32_t)__cvta_generic_to_shared(p);
}
__device__ __forceinline__ void ldsm_x4(uint32_t& r0, uint32_t& r1, uint32_t& r2, uint32_t& r3, uint32_t a) {
    asm volatile("ldmatrix.sync.aligned.m8n8.x4.shared.b16 {%0,%1,%2,%3},[%4];"
                 : "=r"(r0), "=r"(r1), "=r"(r2), "=r"(r3) : "r"(a));
}
__device__ __forceinline__ void mma16816(float* c, const uint32_t* a, const uint32_t* b) {
    asm volatile("mma.sync.aligned.m16n8k16.row.col.f32.f16.f16.f32 "
                 "{%0,%1,%2,%3},{%4,%5,%6,%7},{%8,%9},{%0,%1,%2,%3};"
                 : "+f"(c[0]), "+f"(c[1]), "+f"(c[2]), "+f"(c[3])
                 : "r"(a[0]), "r"(a[1]), "r"(a[2]), "r"(a[3]), "r"(b[0]), "r"(b[1]));
}
// f16-accumulate variant: C/D = 2 regs (f16x2); reg0 = row gid, reg1 = row gid+8
__device__ __forceinline__ void mma16816_h(uint32_t* c, const uint32_t* a, const uint32_t* b) {
    asm volatile("mma.sync.aligned.m16n8k16.row.col.f16.f16.f16.f16 "
                 "{%0,%1},{%2,%3,%4,%5},{%6,%7},{%0,%1};"
                 : "+r"(c[0]), "+r"(c[1])
                 : "r"(a[0]), "r"(a[1]), "r"(a[2]), "r"(a[3]), "r"(b[0]), "r"(b[1]));
}
__device__ __forceinline__ void cp16(uint32_t s, const void* g) {
    asm volatile("cp.async.cg.shared.global [%0],[%1],16;\n" :: "r"(s), "l"(g) : "memory");
}
#define CP_COMMIT() asm volatile("cp.async.commit_group;\n" ::: "memory")
#define CP_WAIT_N(n) asm volatile("cp.async.wait_group %0;\n" :: "n"(n) : "memory")

// GEMM2 geometry (unchanged): block 128x128, 4 warps 64x64, BK=64, 3 stages.
#define BK 64
#define NSTG 3
#define T_STG 18432          // 128 rows * 144 B
#define A_OFF(st) ((st)*T_STG)
#define B_OFF(st) (NSTG*T_STG + (st)*T_STG)
#define SMEM_GEMM (2*NSTG*T_STG)   // 110592

// GEMM1 geometry: block 128M x 256N (128g+128u), 256 threads (8 warps, 2M x 4N),
// warp 64x64, f16 accumulators, BK=64, 2 stages. smem 108KB -> 2 blocks/SM.
#define G1_A_OFF(st) ((st)*18432)
#define G1_B_OFF(st) (36864 + (st)*36864)   // B: 256 rows * 144 B per stage
#define SMEM_G1 110592

#define N13 ((size_t)NEXP*2*HID*DIM)

// ---------------- weight conversion (fp32 -> fp16) ----------------
__global__ void k_conv(const float* __restrict__ w13, const float* __restrict__ w2) {
    size_t i = ((size_t)blockIdx.x * 256 + threadIdx.x) * 4;
    if (i < N13) {
        float4 v = *reinterpret_cast<const float4*>(w13 + i);
        *reinterpret_cast<__half2*>(g_w13h + i)     = __floats2half2_rn(v.x, v.y);
        *reinterpret_cast<__half2*>(g_w13h + i + 2) = __floats2half2_rn(v.z, v.w);
    } else {
        size_t j = i - N13;
        float4 v = *reinterpret_cast<const float4*>(w2 + j);
        *reinterpret_cast<__half2*>(g_w2h + j)     = __floats2half2_rn(v.x, v.y);
        *reinterpret_cast<__half2*>(g_w2h + j + 2) = __floats2half2_rn(v.z, v.w);
    }
}

// ---------------- router (+ fused per-chunk expert count) ----------------
__global__ void k_router(const float* __restrict__ x, const float* __restrict__ gw) {
    __shared__ int se[16];
    const int warp = threadIdx.x >> 5, lane = threadIdx.x & 31;
    const int t = blockIdx.x * 8 + warp;
    float acc[NEXP];
    #pragma unroll
    for (int e = 0; e < NEXP; e++) acc[e] = 0.f;
    const float* xr = x + (size_t)t * DIM;
    for (int i = lane; i < DIM; i += 32) {
        float xv = xr[i];
        #pragma unroll
        for (int e = 0; e < NEXP; e++) acc[e] += xv * gw[e * DIM + i];
    }
    #pragma unroll
    for (int e = 0; e < NEXP; e++) {
        #pragma unroll
        for (int off = 16; off; off >>= 1)
            acc[e] += __shfl_xor_sync(0xffffffffu, acc[e], off);
    }
    if (lane == 0) {
        int e1 = 0; float l1 = acc[0];
        #pragma unroll
        for (int e = 1; e < NEXP; e++) if (acc[e] > l1) { l1 = acc[e]; e1 = e; }
        int e2 = (e1 == 0) ? 1 : 0; float l2 = acc[e2];
        #pragma unroll
        for (int e = 0; e < NEXP; e++)
            if (e != e1 && acc[e] > l2) { l2 = acc[e]; e2 = e; }
        float w1 = 1.f / (1.f + expf(l2 - l1));
        g_pair_expert[2 * t]     = e1;
        g_pair_expert[2 * t + 1] = e2;
        g_pair_weight[2 * t]     = w1;
        g_pair_weight[2 * t + 1] = 1.f - w1;
        se[2 * warp]     = e1;
        se[2 * warp + 1] = e2;
    }
    __syncthreads();
    if (threadIdx.x < NEXP) {
        int cnt = 0;
        #pragma unroll
        for (int i = 0; i < 16; i++) cnt += (se[i] == (int)threadIdx.x);
        g_ch_cnt[blockIdx.x][threadIdx.x] = cnt;
    }
}

// ---------------- dispatch: scan / scatter ----------------
__global__ __launch_bounds__(1024) void k_scan() {
    __shared__ int s[1024][NEXP];
    const int t = threadIdx.x;
    int a[NEXP], b[NEXP], tot[NEXP];
    #pragma unroll
    for (int e = 0; e < NEXP; e++) {
        a[e] = g_ch_cnt[2 * t][e];
        b[e] = g_ch_cnt[2 * t + 1][e];
        tot[e] = a[e] + b[e];
        s[t][e] = tot[e];
    }
    __syncthreads();
    for (int off = 1; off < 1024; off <<= 1) {
        int v[NEXP];
        #pragma unroll
        for (int e = 0; e < NEXP; e++)
            v[e] = s[t][e] + ((t >= off) ? s[t - off][e] : 0);
        __syncthreads();
        #pragma unroll
        for (int e = 0; e < NEXP; e++) s[t][e] = v[e];
        __syncthreads();
    }
    #pragma unroll
    for (int e = 0; e < NEXP; e++) {
        int excl = s[t][e] - tot[e];
        g_ch_base[2 * t][e] = excl;
        g_ch_base[2 * t + 1][e] = excl + a[e];
    }
    if (t < NEXP) g_count[t] = min(s[1023][t], CAP);
}

__global__ void k_scatter() {
    int c = blockIdx.x * 64 + threadIdx.x;
    int base[NEXP];
    #pragma unroll
    for (int e = 0; e < NEXP; e++) base[e] = g_ch_base[c][e];
    const int4* ep = reinterpret_cast<const int4*>(g_pair_expert + c * 16);
    #pragma unroll
    for (int i = 0; i < 4; i++) {
        int4 v = ep[i];
        int es[4] = {v.x, v.y, v.z, v.w};
        #pragma unroll
        for (int q = 0; q < 4; q++) {
            int p = c * 16 + i * 4 + q;
            int eq = es[q];
            int pos = 0;
            #pragma unroll
            for (int e = 0; e < NEXP; e++)
                if (eq == e) { pos = base[e]; base[e] = pos + 1; }
            if (pos < CAP) {
                int slot = eq * CAP + pos;
                g_pair_slot[p] = slot;
                g_slot_token[slot] = p >> 1;
            } else {
                g_pair_slot[p] = -1;
            }
        }
    }
}

// ---------------- zbuf: RMSNorm(2x)*norm_w -> fp16 (192 threads, float4) ----------------
__global__ void k_zbuf(const float* __restrict__ x, const float* __restrict__ nw) {
    const int slot = blockIdx.x;
    const int e = slot / CAP;
    const int tid = threadIdx.x;
    __half* zr = g_zbuf + (size_t)slot * DIM;
    const int local = slot - e * CAP;
    const int cnt = g_count[e];
    if (local >= cnt) {
        if (local < ((cnt + 127) & ~127))
            reinterpret_cast<uint2*>(zr)[tid] = make_uint2(0u, 0u);
        return;
    }
    const int t = g_slot_token[slot];
    float4 v = reinterpret_cast<const float4*>(x + (size_t)t * DIM)[tid];
    float ss = v.x * v.x + v.y * v.y + v.z * v.z + v.w * v.w;
    #pragma unroll
    for (int off = 16; off; off >>= 1) ss += __shfl_xor_sync(0xffffffffu, ss, off);
    __shared__ float red[6];
    if ((tid & 31) == 0) red[tid >> 5] = ss;
    __syncthreads();
    float tot = 0.f;
    #pragma unroll
    for (int w = 0; w < 6; w++) tot += red[w];
    float scale = rsqrtf(4.f * tot / (float)DIM + 1e-6f) * 2.f;
    float4 w4 = reinterpret_cast<const float4*>(nw + (size_t)e * DIM)[tid];
    __half2 h0 = __floats2half2_rn(v.x * scale * w4.x, v.y * scale * w4.y);
    __half2 h1 = __floats2half2_rn(v.z * scale * w4.z, v.w * scale * w4.w);
    uint2 o;
    o.x = *reinterpret_cast<uint32_t*>(&h0);
    o.y = *reinterpret_cast<uint32_t*>(&h1);
    reinterpret_cast<uint2*>(zr)[tid] = o;
}

// ---------------- GEMM1: 128M x 256acc (128g+128u), 8 warps 64x64, f16 acc ----------------
// B smem rows r: pair=r>>6, half=(r>>5)&1, off=r&31 -> hcol jb+pair*32+off,
// src g (half=0) / u (half=1). Warp wn covers rows [wn*64, wn*64+64):
// j<4 -> g rows wn*64+j*8 ; j>=4 -> u rows wn*64+32+(j-4)*8. SwiGLU warp-local.
__global__ __launch_bounds__(256, 2) void k_gemm1() {
    extern __shared__ char smem[];
    const int e = blockIdx.z;
    const int row0 = blockIdx.y * 128;
    if (row0 >= g_count[e]) return;
    const int jb = blockIdx.x * 128;               // 128 h-cols per block
    const uint32_t sb = smem_u32(smem);
    const int tid = threadIdx.x, lane = tid & 31, wid = tid >> 5;
    const int wm = wid >> 2, wn = wid & 3;
    const int m0 = wm * 64;

    const __half* Ag  = g_zbuf + (size_t)(e * CAP + row0) * DIM;
    const __half* Bgg = g_w13h + (size_t)e * (2 * HID) * DIM + (size_t)jb * DIM;
    const __half* Bgu = g_w13h + (size_t)e * (2 * HID) * DIM + (size_t)(HID + jb) * DIM;

    uint32_t hacc[4][8][2];
    #pragma unroll
    for (int i = 0; i < 4; i++)
        #pragma unroll
        for (int j = 0; j < 8; j++) { hacc[i][j][0] = 0u; hacc[i][j][1] = 0u; }

    auto load_tile = [&](int st, int kt) {
        const int k0 = kt * BK;
        // A: 1024 chunks (128 rows x 8)
        #pragma unroll
        for (int i = 0; i < 4; i++) {
            int id = tid + i * 256;
            int row = id >> 3, c16 = id & 7;
            cp16(sb + G1_A_OFF(st) + row * 144 + c16 * 16, Ag + (size_t)row * DIM + k0 + c16 * 8);
        }
        // B: 2048 chunks (256 rows x 8), g/u interleaved in 32-row groups
        #pragma unroll
        for (int i = 0; i < 8; i++) {
            int id = tid + i * 256;
            int row = id >> 3, c16 = id & 7;
            int pair = row >> 6, off = row & 31;
            const __half* bs = ((row >> 5) & 1) ? Bgu : Bgg;
            cp16(sb + G1_B_OFF(st) + row * 144 + c16 * 16,
                 bs + (size_t)(pair * 32 + off) * DIM + k0 + c16 * 8);
        }
        CP_COMMIT();
    };

    const int KT = DIM / BK;                       // 12
    load_tile(0, 0);

    #pragma unroll 1
    for (int kt = 0; kt < KT; kt++) {
        CP_WAIT_N(0);
        __syncthreads();
        if (kt + 1 < KT) load_tile((kt + 1) & 1, kt + 1);
        const int st = kt & 1;
        #pragma unroll
        for (int ka = 0; ka < 4; ka++) {
            uint32_t af[4][4];
            #pragma unroll
            for (int i = 0; i < 4; i++) {
                uint32_t addr = sb + G1_A_OFF(st) + (m0 + i * 16 + (lane & 15)) * 144
                              + ka * 32 + ((lane >> 4) << 4);
                ldsm_x4(af[i][0], af[i][1], af[i][2], af[i][3], addr);
            }
            uint32_t bf[8][2];
            #pragma unroll
            for (int jp = 0; jp < 4; jp++) {
                int j0 = jp * 2;
                int m = lane >> 3;
                int jj = j0 + (m >> 1);
                int brow = (jj < 4) ? (wn * 64 + jj * 8) : (wn * 64 + 32 + (jj - 4) * 8);
                uint32_t addr = sb + G1_B_OFF(st) + (brow + (lane & 7)) * 144
                              + ka * 32 + ((m & 1) << 4);
                uint32_t r0, r1, r2, r3;
                ldsm_x4(r0, r1, r2, r3, addr);
                bf[j0][0] = r0; bf[j0][1] = r1;
                bf[j0 + 1][0] = r2; bf[j0 + 1][1] = r3;
            }
            #pragma unroll
            for (int i = 0; i < 4; i++)
                #pragma unroll
                for (int j = 0; j < 8; j++)
                    mma16816_h(hacc[i][j], af[i], bf[j]);
        }
    }

    // epilogue: h = silu(g)*u ; j<4 g, j>=4 u, same h cols (warp-local)
    const int gid = lane >> 2, qid = lane & 3;
    __half* Hb = g_hbuf + (size_t)(e * CAP + row0) * HID + jb;
    #pragma unroll
    for (int i = 0; i < 4; i++) {
        #pragma unroll
        for (int j = 0; j < 4; j++) {
            int hc = wn * 32 + j * 8 + qid * 2;
            #pragma unroll
            for (int half = 0; half < 2; half++) {
                int r = m0 + i * 16 + gid + half * 8;
                float2 gg = __half22float2(*reinterpret_cast<__half2*>(&hacc[i][j][half]));
                float2 uu = __half22float2(*reinterpret_cast<__half2*>(&hacc[i][j + 4][half]));
                float h0 = gg.x * uu.x / (1.f + __expf(-gg.x));
                float h1 = gg.y * uu.y / (1.f + __expf(-gg.y));
                *reinterpret_cast<__half2*>(Hb + (size_t)r * HID + hc) =
                    __floats2half2_rn(h0, h1);
            }
        }
    }
}

// ---------------- GEMM2: 128M x 128N, 4 warps 64x64, BK=64, f32 acc, fp16 out ----------------
__global__ __launch_bounds__(128) void k_gemm2() {
    extern __shared__ char smem[];
    const int e = blockIdx.z;
    const int row0 = blockIdx.y * 128;
    if (row0 >= g_count[e]) return;
    const int db = blockIdx.x * 128;
    const uint32_t sb = smem_u32(smem);
    const int tid = threadIdx.x, lane = tid & 31, wid = tid >> 5;
    const int wm = wid & 1, wn = wid >> 1;
    const int m0 = wm * 64;

    const __half* Ag = g_hbuf + (size_t)(e * CAP + row0) * HID;
    const __half* Bg = g_w2h + (size_t)e * DIM * HID + (size_t)db * HID;

    float acc[4][8][4];
    #pragma unroll
    for (int i = 0; i < 4; i++)
        #pragma unroll
        for (int j = 0; j < 8; j++)
            #pragma unroll
            for (int q = 0; q < 4; q++) acc[i][j][q] = 0.f;

    auto load_tile = [&](int st, int kt) {
        const int k0 = kt * BK;
        #pragma unroll
        for (int i = 0; i < 8; i++) {
            int id = tid + i * 128;
            int row = id >> 3, c16 = id & 7;
            cp16(sb + A_OFF(st) + row * 144 + c16 * 16, Ag + (size_t)row * HID + k0 + c16 * 8);
            cp16(sb + B_OFF(st) + row * 144 + c16 * 16, Bg + (size_t)row * HID + k0 + c16 * 8);
        }
        CP_COMMIT();
    };

    const int KT = HID / BK;                       // 32
    load_tile(0, 0); load_tile(1, 1);

    #pragma unroll 1
    for (int kt = 0; kt < KT; kt++) {
        if (kt < KT - 1) CP_WAIT_N(1); else CP_WAIT_N(0);
        __syncthreads();
        if (kt + 2 < KT) load_tile((kt + 2) % 3, kt + 2);
        const int st = kt % 3;
        #pragma unroll
        for (int ka = 0; ka < 4; ka++) {
            uint32_t af[4][4];
            #pragma unroll
            for (int i = 0; i < 4; i++) {
                uint32_t addr = sb + A_OFF(st) + (m0 + i * 16 + (lane & 15)) * 144
                              + ka * 32 + ((lane >> 4) << 4);
                ldsm_x4(af[i][0], af[i][1], af[i][2], af[i][3], addr);
            }
            uint32_t bf[8][2];
            #pragma unroll
            for (int jp = 0; jp < 4; jp++) {
                int j0 = jp * 2;
                int m = lane >> 3;
                int jj = j0 + (m >> 1);
                int brow = wn * 64 + jj * 8;
                uint32_t addr = sb + B_OFF(st) + (brow + (lane & 7)) * 144
                              + ka * 32 + ((m & 1) << 4);
                uint32_t r0, r1, r2, r3;
                ldsm_x4(r0, r1, r2, r3, addr);
                bf[j0][0] = r0; bf[j0][1] = r1;
                bf[j0 + 1][0] = r2; bf[j0 + 1][1] = r3;
            }
            #pragma unroll
            for (int i = 0; i < 4; i++)
                #pragma unroll
                for (int j = 0; j < 8; j++)
                    mma16816(acc[i][j], af[i], bf[j]);
        }
    }

    const int gid = lane >> 2, qid = lane & 3;
    __half* Yb = g_ybuf + (size_t)(e * CAP + row0) * DIM + db;
    #pragma unroll
    for (int i = 0; i < 4; i++) {
        #pragma unroll
        for (int j = 0; j < 8; j++) {
            int dc = wn * 64 + j * 8 + qid * 2;
            #pragma unroll
            for (int half = 0; half < 2; half++) {
                int r = m0 + i * 16 + gid + half * 8;
                *reinterpret_cast<__half2*>(Yb + (size_t)r * DIM + dc) =
                    __floats2half2_rn(acc[i][j][half * 2 + 0], acc[i][j][half * 2 + 1]);
            }
        }
    }
}

// ---------------- combine (192 threads, float4 x / half2 y) ----------------
__global__ void k_combine(const float* __restrict__ x, float* __restrict__ out) {
    const int t = blockIdx.x, tid = threadIdx.x;
    int s0 = g_pair_slot[2 * t], s1 = g_pair_slot[2 * t + 1];
    float w0 = g_pair_weight[2 * t], w1 = g_pair_weight[2 * t + 1];
    if (s0 < 0) w0 = 0.f;
    if (s1 < 0) w1 = 0.f;
    const float wsum = w0 + w1;
    float4 xv = reinterpret_cast<const float4*>(x + (size_t)t * DIM)[tid];
    float4 a;
    a.x = wsum * xv.x; a.y = wsum * xv.y; a.z = wsum * xv.z; a.w = wsum * xv.w;
    if (s0 >= 0) {
        uint2 yp = reinterpret_cast<const uint2*>(g_ybuf + (size_t)s0 * DIM)[tid];
        float2 lo = __half22float2(*reinterpret_cast<__half2*>(&yp.x));
        float2 hi = __half22float2(*reinterpret_cast<__half2*>(&yp.y));
        a.x += w0 * lo.x; a.y += w0 * lo.y; a.z += w0 * hi.x; a.w += w0 * hi.y;
    }
    if (s1 >= 0) {
        uint2 yp = reinterpret_cast<const uint2*>(g_ybuf + (size_t)s1 * DIM)[tid];
        float2 lo = __half22float2(*reinterpret_cast<__half2*>(&yp.x));
        float2 hi = __half22float2(*reinterpret_cast<__half2*>(&yp.y));
        a.x += w1 * lo.x; a.y += w1 * lo.y; a.z += w1 * hi.x; a.w += w1 * hi.y;
    }
    reinterpret_cast<float4*>(out + (size_t)t * DIM)[tid] = a;
}

// ---------------- launch ----------------
extern "C" void kernel_launch(void* const* d_in, const int* in_sizes, int n_in,
                              void* d_out, int out_size) {
    const float* x      = (const float*)d_in[0];
    const float* gate_w = (const float*)d_in[1];
    const float* w13    = (const float*)d_in[2];
    const float* w2     = (const float*)d_in[3];
    const float* norm_w = (const float*)d_in[4];
    float* out = (float*)d_out;

    cudaFuncSetAttribute(k_gemm1, cudaFuncAttributeMaxDynamicSharedMemorySize, SMEM_G1);
    cudaFuncSetAttribute(k_gemm2, cudaFuncAttributeMaxDynamicSharedMemorySize, SMEM_GEMM);

    const int conv_blocks = (int)((N13 + (size_t)NEXP * DIM * HID) / 1024);
    k_conv<<<conv_blocks, 256>>>(w13, w2);
    k_router<<<NCH, 256>>>(x, gate_w);
    k_scan<<<1, 1024>>>();
    k_scatter<<<32, 64>>>();
    k_zbuf<<<ECAP, 192>>>(x, norm_w);
    k_gemm1<<<dim3(HID / 128, CAP / 128, NEXP), 256, SMEM_G1>>>();
    k_gemm2<<<dim3(DIM / 128, CAP / 128, NEXP), 128, SMEM_GEMM>>>();
    k_combine<<<N_TOK, 192>>>(x, out);
}

// round 15
// speedup vs baseline: 1.4697x; 1.4697x over previous
#include <cuda_runtime.h>
#include <cuda_fp16.h>
#include <math.h>
#include <stdint.h>

#define N_TOK 16384
#define DIM 768
#define NEXP 8
#define HID 2048
#define CAP 5120
#define ECAP (NEXP*CAP)
#define NP (N_TOK*2)
#define NCH 2048

// ---------------- device scratch ----------------
__device__ int   g_pair_expert[NP];
__device__ float g_pair_weight[NP];
__device__ int   g_pair_slot[NP];
__device__ int   g_slot_token[ECAP];
__device__ int   g_count[NEXP];
__device__ int   g_ch_cnt[NCH][NEXP];
__device__ int   g_ch_base[NCH][NEXP];
__device__ __half g_w13h[(size_t)NEXP*2*HID*DIM];
__device__ __half g_w2h [(size_t)NEXP*DIM*HID];
__device__ __half g_zbuf[(size_t)ECAP*DIM];
__device__ __half g_hbuf[(size_t)ECAP*HID];
__device__ __half g_ybuf[(size_t)ECAP*DIM];

// ---------------- helpers ----------------
__device__ __forceinline__ uint32_t smem_u32(const void* p) {
    return (uint32_t)__cvta_generic_to_shared(p);
}
__device__ __forceinline__ void ldsm_x4(uint32_t& r0, uint32_t& r1, uint32_t& r2, uint32_t& r3, uint32_t a) {
    asm volatile("ldmatrix.sync.aligned.m8n8.x4.shared.b16 {%0,%1,%2,%3},[%4];"
                 : "=r"(r0), "=r"(r1), "=r"(r2), "=r"(r3) : "r"(a));
}
__device__ __forceinline__ void mma16816(float* c, const uint32_t* a, const uint32_t* b) {
    asm volatile("mma.sync.aligned.m16n8k16.row.col.f32.f16.f16.f32 "
                 "{%0,%1,%2,%3},{%4,%5,%6,%7},{%8,%9},{%0,%1,%2,%3};"
                 : "+f"(c[0]), "+f"(c[1]), "+f"(c[2]), "+f"(c[3])
                 : "r"(a[0]), "r"(a[1]), "r"(a[2]), "r"(a[3]), "r"(b[0]), "r"(b[1]));
}
// f16-accumulate variant: C/D = 2 regs (f16x2); reg0 = row gid, reg1 = row gid+8
__device__ __forceinline__ void mma16816_h(uint32_t* c, const uint32_t* a, const uint32_t* b) {
    asm volatile("mma.sync.aligned.m16n8k16.row.col.f16.f16.f16.f16 "
                 "{%0,%1},{%2,%3,%4,%5},{%6,%7},{%0,%1};"
                 : "+r"(c[0]), "+r"(c[1])
                 : "r"(a[0]), "r"(a[1]), "r"(a[2]), "r"(a[3]), "r"(b[0]), "r"(b[1]));
}
__device__ __forceinline__ void cp16(uint32_t s, const void* g) {
    asm volatile("cp.async.cg.shared.global [%0],[%1],16;\n" :: "r"(s), "l"(g) : "memory");
}
#define CP_COMMIT() asm volatile("cp.async.commit_group;\n" ::: "memory")
#define CP_WAIT_N(n) asm volatile("cp.async.wait_group %0;\n" :: "n"(n) : "memory")

// GEMM2 geometry: block 128M x 128N, 128 threads (4 warps, 2M x 2N), warp 64x64,
// BK=64, 3 stages. Row stride 144B (conflict-free). smem 108KB -> 2 blocks/SM.
#define BK 64
#define NSTG 3
#define T_STG 18432          // 128 rows * 144 B
#define A_OFF(st) ((st)*T_STG)
#define B_OFF(st) (NSTG*T_STG + (st)*T_STG)
#define SMEM_GEMM (2*NSTG*T_STG)   // 110592

// GEMM1: same block geometry but f16 accumulators + 2 stages -> 72KB smem,
// ~150 regs -> 3 blocks/SM (12 warps).
#define G1A_OFF(st) ((st)*T_STG)
#define G1B_OFF(st) (2*T_STG + (st)*T_STG)
#define SMEM_G1 (4*T_STG)          // 73728

#define N13 ((size_t)NEXP*2*HID*DIM)

// ---------------- weight conversion (fp32 -> fp16) ----------------
__global__ void k_conv(const float* __restrict__ w13, const float* __restrict__ w2) {
    size_t i = ((size_t)blockIdx.x * 256 + threadIdx.x) * 4;
    if (i < N13) {
        float4 v = *reinterpret_cast<const float4*>(w13 + i);
        *reinterpret_cast<__half2*>(g_w13h + i)     = __floats2half2_rn(v.x, v.y);
        *reinterpret_cast<__half2*>(g_w13h + i + 2) = __floats2half2_rn(v.z, v.w);
    } else {
        size_t j = i - N13;
        float4 v = *reinterpret_cast<const float4*>(w2 + j);
        *reinterpret_cast<__half2*>(g_w2h + j)     = __floats2half2_rn(v.x, v.y);
        *reinterpret_cast<__half2*>(g_w2h + j + 2) = __floats2half2_rn(v.z, v.w);
    }
}

// ---------------- router (+ fused per-chunk expert count) ----------------
__global__ void k_router(const float* __restrict__ x, const float* __restrict__ gw) {
    __shared__ int se[16];
    const int warp = threadIdx.x >> 5, lane = threadIdx.x & 31;
    const int t = blockIdx.x * 8 + warp;
    float acc[NEXP];
    #pragma unroll
    for (int e = 0; e < NEXP; e++) acc[e] = 0.f;
    const float* xr = x + (size_t)t * DIM;
    for (int i = lane; i < DIM; i += 32) {
        float xv = xr[i];
        #pragma unroll
        for (int e = 0; e < NEXP; e++) acc[e] += xv * gw[e * DIM + i];
    }
    #pragma unroll
    for (int e = 0; e < NEXP; e++) {
        #pragma unroll
        for (int off = 16; off; off >>= 1)
            acc[e] += __shfl_xor_sync(0xffffffffu, acc[e], off);
    }
    if (lane == 0) {
        int e1 = 0; float l1 = acc[0];
        #pragma unroll
        for (int e = 1; e < NEXP; e++) if (acc[e] > l1) { l1 = acc[e]; e1 = e; }
        int e2 = (e1 == 0) ? 1 : 0; float l2 = acc[e2];
        #pragma unroll
        for (int e = 0; e < NEXP; e++)
            if (e != e1 && acc[e] > l2) { l2 = acc[e]; e2 = e; }
        float w1 = 1.f / (1.f + expf(l2 - l1));
        g_pair_expert[2 * t]     = e1;
        g_pair_expert[2 * t + 1] = e2;
        g_pair_weight[2 * t]     = w1;
        g_pair_weight[2 * t + 1] = 1.f - w1;
        se[2 * warp]     = e1;
        se[2 * warp + 1] = e2;
    }
    __syncthreads();
    if (threadIdx.x < NEXP) {
        int cnt = 0;
        #pragma unroll
        for (int i = 0; i < 16; i++) cnt += (se[i] == (int)threadIdx.x);
        g_ch_cnt[blockIdx.x][threadIdx.x] = cnt;
    }
}

// ---------------- dispatch: scan / scatter ----------------
__global__ __launch_bounds__(1024) void k_scan() {
    __shared__ int s[1024][NEXP];
    const int t = threadIdx.x;
    int a[NEXP], b[NEXP], tot[NEXP];
    #pragma unroll
    for (int e = 0; e < NEXP; e++) {
        a[e] = g_ch_cnt[2 * t][e];
        b[e] = g_ch_cnt[2 * t + 1][e];
        tot[e] = a[e] + b[e];
        s[t][e] = tot[e];
    }
    __syncthreads();
    for (int off = 1; off < 1024; off <<= 1) {
        int v[NEXP];
        #pragma unroll
        for (int e = 0; e < NEXP; e++)
            v[e] = s[t][e] + ((t >= off) ? s[t - off][e] : 0);
        __syncthreads();
        #pragma unroll
        for (int e = 0; e < NEXP; e++) s[t][e] = v[e];
        __syncthreads();
    }
    #pragma unroll
    for (int e = 0; e < NEXP; e++) {
        int excl = s[t][e] - tot[e];
        g_ch_base[2 * t][e] = excl;
        g_ch_base[2 * t + 1][e] = excl + a[e];
    }
    if (t < NEXP) g_count[t] = min(s[1023][t], CAP);
}

__global__ void k_scatter() {
    int c = blockIdx.x * 64 + threadIdx.x;
    int base[NEXP];
    #pragma unroll
    for (int e = 0; e < NEXP; e++) base[e] = g_ch_base[c][e];
    const int4* ep = reinterpret_cast<const int4*>(g_pair_expert + c * 16);
    #pragma unroll
    for (int i = 0; i < 4; i++) {
        int4 v = ep[i];
        int es[4] = {v.x, v.y, v.z, v.w};
        #pragma unroll
        for (int q = 0; q < 4; q++) {
            int p = c * 16 + i * 4 + q;
            int eq = es[q];
            int pos = 0;
            #pragma unroll
            for (int e = 0; e < NEXP; e++)
                if (eq == e) { pos = base[e]; base[e] = pos + 1; }
            if (pos < CAP) {
                int slot = eq * CAP + pos;
                g_pair_slot[p] = slot;
                g_slot_token[slot] = p >> 1;
            } else {
                g_pair_slot[p] = -1;
            }
        }
    }
}

// ---------------- zbuf: RMSNorm(2x)*norm_w -> fp16 (192 threads, float4) ----------------
__global__ void k_zbuf(const float* __restrict__ x, const float* __restrict__ nw) {
    const int slot = blockIdx.x;
    const int e = slot / CAP;
    const int tid = threadIdx.x;
    __half* zr = g_zbuf + (size_t)slot * DIM;
    const int local = slot - e * CAP;
    const int cnt = g_count[e];
    if (local >= cnt) {
        if (local < ((cnt + 127) & ~127))
            reinterpret_cast<uint2*>(zr)[tid] = make_uint2(0u, 0u);
        return;
    }
    const int t = g_slot_token[slot];
    float4 v = reinterpret_cast<const float4*>(x + (size_t)t * DIM)[tid];
    float ss = v.x * v.x + v.y * v.y + v.z * v.z + v.w * v.w;
    #pragma unroll
    for (int off = 16; off; off >>= 1) ss += __shfl_xor_sync(0xffffffffu, ss, off);
    __shared__ float red[6];
    if ((tid & 31) == 0) red[tid >> 5] = ss;
    __syncthreads();
    float tot = 0.f;
    #pragma unroll
    for (int w = 0; w < 6; w++) tot += red[w];
    float scale = rsqrtf(4.f * tot / (float)DIM + 1e-6f) * 2.f;
    float4 w4 = reinterpret_cast<const float4*>(nw + (size_t)e * DIM)[tid];
    __half2 h0 = __floats2half2_rn(v.x * scale * w4.x, v.y * scale * w4.y);
    __half2 h1 = __floats2half2_rn(v.z * scale * w4.z, v.w * scale * w4.w);
    uint2 o;
    o.x = *reinterpret_cast<uint32_t*>(&h0);
    o.y = *reinterpret_cast<uint32_t*>(&h1);
    reinterpret_cast<uint2*>(zr)[tid] = o;
}

// ---------------- GEMM1: 128M x (64g+64u), 4 warps 64x64, BK=64, f16 acc, 2 stages ----------------
__global__ __launch_bounds__(128, 3) void k_gemm1() {
    extern __shared__ char smem[];
    const int e = blockIdx.z;
    const int row0 = blockIdx.y * 128;
    if (row0 >= g_count[e]) return;
    const int jb = blockIdx.x * 64;
    const uint32_t sb = smem_u32(smem);
    const int tid = threadIdx.x, lane = tid & 31, wid = tid >> 5;
    const int wm = wid & 1, wn = wid >> 1;
    const int m0 = wm * 64;

    const __half* Ag  = g_zbuf + (size_t)(e * CAP + row0) * DIM;
    const __half* Bgg = g_w13h + (size_t)e * (2 * HID) * DIM + (size_t)jb * DIM;
    const __half* Bgu = g_w13h + (size_t)e * (2 * HID) * DIM + (size_t)(HID + jb) * DIM;

    uint32_t hacc[4][8][2];
    #pragma unroll
    for (int i = 0; i < 4; i++)
        #pragma unroll
        for (int j = 0; j < 8; j++) { hacc[i][j][0] = 0u; hacc[i][j][1] = 0u; }

    auto load_tile = [&](int st, int kt) {
        const int k0 = kt * BK;
        #pragma unroll
        for (int i = 0; i < 8; i++) {
            int id = tid + i * 128;
            int row = id >> 3, c16 = id & 7;
            cp16(sb + G1A_OFF(st) + row * 144 + c16 * 16, Ag + (size_t)row * DIM + k0 + c16 * 8);
            const __half* bs = (row < 64) ? (Bgg + (size_t)row * DIM)
                                          : (Bgu + (size_t)(row - 64) * DIM);
            cp16(sb + G1B_OFF(st) + row * 144 + c16 * 16, bs + k0 + c16 * 8);
        }
        CP_COMMIT();
    };

    const int KT = DIM / BK;                       // 12
    load_tile(0, 0);

    #pragma unroll 1
    for (int kt = 0; kt < KT; kt++) {
        CP_WAIT_N(0);
        __syncthreads();   // tile kt visible; buffer (kt+1)&1 free (compute kt-1 done)
        if (kt + 1 < KT) load_tile((kt + 1) & 1, kt + 1);
        const int st = kt & 1;
        #pragma unroll
        for (int ka = 0; ka < 4; ka++) {
            uint32_t af[4][4];
            #pragma unroll
            for (int i = 0; i < 4; i++) {
                uint32_t addr = sb + G1A_OFF(st) + (m0 + i * 16 + (lane & 15)) * 144
                              + ka * 32 + ((lane >> 4) << 4);
                ldsm_x4(af[i][0], af[i][1], af[i][2], af[i][3], addr);
            }
            uint32_t bf[8][2];
            #pragma unroll
            for (int jp = 0; jp < 4; jp++) {
                int j0 = jp * 2;
                int m = lane >> 3;
                int jj = j0 + (m >> 1);
                int brow = (jj < 4) ? (wn * 32 + jj * 8) : (64 + wn * 32 + (jj - 4) * 8);
                uint32_t addr = sb + G1B_OFF(st) + (brow + (lane & 7)) * 144
                              + ka * 32 + ((m & 1) << 4);
                uint32_t r0, r1, r2, r3;
                ldsm_x4(r0, r1, r2, r3, addr);
                bf[j0][0] = r0; bf[j0][1] = r1;
                bf[j0 + 1][0] = r2; bf[j0 + 1][1] = r3;
            }
            #pragma unroll
            for (int i = 0; i < 4; i++)
                #pragma unroll
                for (int j = 0; j < 8; j++)
                    mma16816_h(hacc[i][j], af[i], bf[j]);
        }
        __syncthreads();   // compute done before next iter overwrites buffer st
    }

    // epilogue: h = silu(g)*u ; j<4 g cols, j>=4 u, same h cols
    const int gid = lane >> 2, qid = lane & 3;
    __half* Hb = g_hbuf + (size_t)(e * CAP + row0) * HID + jb;
    #pragma unroll
    for (int i = 0; i < 4; i++) {
        #pragma unroll
        for (int j = 0; j < 4; j++) {
            int hc = wn * 32 + j * 8 + qid * 2;
            #pragma unroll
            for (int half = 0; half < 2; half++) {
                int r = m0 + i * 16 + gid + half * 8;
                float2 gg = __half22float2(*reinterpret_cast<__half2*>(&hacc[i][j][half]));
                float2 uu = __half22float2(*reinterpret_cast<__half2*>(&hacc[i][j + 4][half]));
                float h0 = gg.x * uu.x / (1.f + __expf(-gg.x));
                float h1 = gg.y * uu.y / (1.f + __expf(-gg.y));
                *reinterpret_cast<__half2*>(Hb + (size_t)r * HID + hc) =
                    __floats2half2_rn(h0, h1);
            }
        }
    }
}

// ---------------- GEMM2: 128M x 128N, 4 warps 64x64, BK=64, f32 acc, fp16 out ----------------
__global__ __launch_bounds__(128) void k_gemm2() {
    extern __shared__ char smem[];
    const int e = blockIdx.z;
    const int row0 = blockIdx.y * 128;
    if (row0 >= g_count[e]) return;
    const int db = blockIdx.x * 128;
    const uint32_t sb = smem_u32(smem);
    const int tid = threadIdx.x, lane = tid & 31, wid = tid >> 5;
    const int wm = wid & 1, wn = wid >> 1;
    const int m0 = wm * 64;

    const __half* Ag = g_hbuf + (size_t)(e * CAP + row0) * HID;
    const __half* Bg = g_w2h + (size_t)e * DIM * HID + (size_t)db * HID;

    float acc[4][8][4];
    #pragma unroll
    for (int i = 0; i < 4; i++)
        #pragma unroll
        for (int j = 0; j < 8; j++)
            #pragma unroll
            for (int q = 0; q < 4; q++) acc[i][j][q] = 0.f;

    auto load_tile = [&](int st, int kt) {
        const int k0 = kt * BK;
        #pragma unroll
        for (int i = 0; i < 8; i++) {
            int id = tid + i * 128;
            int row = id >> 3, c16 = id & 7;
            cp16(sb + A_OFF(st) + row * 144 + c16 * 16, Ag + (size_t)row * HID + k0 + c16 * 8);
            cp16(sb + B_OFF(st) + row * 144 + c16 * 16, Bg + (size_t)row * HID + k0 + c16 * 8);
        }
        CP_COMMIT();
    };

    const int KT = HID / BK;                       // 32
    load_tile(0, 0); load_tile(1, 1);

    #pragma unroll 1
    for (int kt = 0; kt < KT; kt++) {
        if (kt < KT - 1) CP_WAIT_N(1); else CP_WAIT_N(0);
        __syncthreads();
        if (kt + 2 < KT) load_tile((kt + 2) % 3, kt + 2);
        const int st = kt % 3;
        #pragma unroll
        for (int ka = 0; ka < 4; ka++) {
            uint32_t af[4][4];
            #pragma unroll
            for (int i = 0; i < 4; i++) {
                uint32_t addr = sb + A_OFF(st) + (m0 + i * 16 + (lane & 15)) * 144
                              + ka * 32 + ((lane >> 4) << 4);
                ldsm_x4(af[i][0], af[i][1], af[i][2], af[i][3], addr);
            }
            uint32_t bf[8][2];
            #pragma unroll
            for (int jp = 0; jp < 4; jp++) {
                int j0 = jp * 2;
                int m = lane >> 3;
                int jj = j0 + (m >> 1);
                int brow = wn * 64 + jj * 8;
                uint32_t addr = sb + B_OFF(st) + (brow + (lane & 7)) * 144
                              + ka * 32 + ((m & 1) << 4);
                uint32_t r0, r1, r2, r3;
                ldsm_x4(r0, r1, r2, r3, addr);
                bf[j0][0] = r0; bf[j0][1] = r1;
                bf[j0 + 1][0] = r2; bf[j0 + 1][1] = r3;
            }
            #pragma unroll
            for (int i = 0; i < 4; i++)
                #pragma unroll
                for (int j = 0; j < 8; j++)
                    mma16816(acc[i][j], af[i], bf[j]);
        }
    }

    const int gid = lane >> 2, qid = lane & 3;
    __half* Yb = g_ybuf + (size_t)(e * CAP + row0) * DIM + db;
    #pragma unroll
    for (int i = 0; i < 4; i++) {
        #pragma unroll
        for (int j = 0; j < 8; j++) {
            int dc = wn * 64 + j * 8 + qid * 2;
            #pragma unroll
            for (int half = 0; half < 2; half++) {
                int r = m0 + i * 16 + gid + half * 8;
                *reinterpret_cast<__half2*>(Yb + (size_t)r * DIM + dc) =
                    __floats2half2_rn(acc[i][j][half * 2 + 0], acc[i][j][half * 2 + 1]);
            }
        }
    }
}

// ---------------- combine (192 threads, float4 x / half2 y) ----------------
__global__ void k_combine(const float* __restrict__ x, float* __restrict__ out) {
    const int t = blockIdx.x, tid = threadIdx.x;
    int s0 = g_pair_slot[2 * t], s1 = g_pair_slot[2 * t + 1];
    float w0 = g_pair_weight[2 * t], w1 = g_pair_weight[2 * t + 1];
    if (s0 < 0) w0 = 0.f;
    if (s1 < 0) w1 = 0.f;
    const float wsum = w0 + w1;
    float4 xv = reinterpret_cast<const float4*>(x + (size_t)t * DIM)[tid];
    float4 a;
    a.x = wsum * xv.x; a.y = wsum * xv.y; a.z = wsum * xv.z; a.w = wsum * xv.w;
    if (s0 >= 0) {
        uint2 yp = reinterpret_cast<const uint2*>(g_ybuf + (size_t)s0 * DIM)[tid];
        float2 lo = __half22float2(*reinterpret_cast<__half2*>(&yp.x));
        float2 hi = __half22float2(*reinterpret_cast<__half2*>(&yp.y));
        a.x += w0 * lo.x; a.y += w0 * lo.y; a.z += w0 * hi.x; a.w += w0 * hi.y;
    }
    if (s1 >= 0) {
        uint2 yp = reinterpret_cast<const uint2*>(g_ybuf + (size_t)s1 * DIM)[tid];
        float2 lo = __half22float2(*reinterpret_cast<__half2*>(&yp.x));
        float2 hi = __half22float2(*reinterpret_cast<__half2*>(&yp.y));
        a.x += w1 * lo.x; a.y += w1 * lo.y; a.z += w1 * hi.x; a.w += w1 * hi.y;
    }
    reinterpret_cast<float4*>(out + (size_t)t * DIM)[tid] = a;
}

// ---------------- launch ----------------
extern "C" void kernel_launch(void* const* d_in, const int* in_sizes, int n_in,
                              void* d_out, int out_size) {
    const float* x      = (const float*)d_in[0];
    const float* gate_w = (const float*)d_in[1];
    const float* w13    = (const float*)d_in[2];
    const float* w2     = (const float*)d_in[3];
    const float* norm_w = (const float*)d_in[4];
    float* out = (float*)d_out;

    cudaFuncSetAttribute(k_gemm1, cudaFuncAttributeMaxDynamicSharedMemorySize, SMEM_G1);
    cudaFuncSetAttribute(k_gemm2, cudaFuncAttributeMaxDynamicSharedMemorySize, SMEM_GEMM);

    const int conv_blocks = (int)((N13 + (size_t)NEXP * DIM * HID) / 1024);
    k_conv<<<conv_blocks, 256>>>(w13, w2);
    k_router<<<NCH, 256>>>(x, gate_w);
    k_scan<<<1, 1024>>>();
    k_scatter<<<32, 64>>>();
    k_zbuf<<<ECAP, 192>>>(x, norm_w);
    k_gemm1<<<dim3(HID / 64, CAP / 128, NEXP), 128, SMEM_G1>>>();
    k_gemm2<<<dim3(DIM / 128, CAP / 128, NEXP), 128, SMEM_GEMM>>>();
    k_combine<<<N_TOK, 192>>>(x, out);
}

// round 16
// speedup vs baseline: 1.5304x; 1.0413x over previous
#include <cuda_runtime.h>
#include <cuda_fp16.h>
#include <math.h>
#include <stdint.h>

#define N_TOK 16384
#define DIM 768
#define NEXP 8
#define HID 2048
#define CAP 5120
#define ECAP (NEXP*CAP)
#define NP (N_TOK*2)
#define NCH 2048

// ---------------- device scratch ----------------
__device__ int   g_pair_expert[NP];
__device__ float g_pair_weight[NP];
__device__ int   g_pair_slot[NP];
__device__ int   g_slot_token[ECAP];
__device__ int   g_count[NEXP];
__device__ int   g_ch_cnt[NCH][NEXP];
__device__ int   g_ch_base[NCH][NEXP];
__device__ __half g_w13h[(size_t)NEXP*2*HID*DIM];
__device__ __half g_w2h [(size_t)NEXP*DIM*HID];
__device__ __half g_zbuf[(size_t)ECAP*DIM];
__device__ __half g_hbuf[(size_t)ECAP*HID];
__device__ __half g_ybuf[(size_t)ECAP*DIM];

// ---------------- helpers ----------------
__device__ __forceinline__ uint32_t smem_u32(const void* p) {
    return (uint32_t)__cvta_generic_to_shared(p);
}
__device__ __forceinline__ void ldsm_x4(uint32_t& r0, uint32_t& r1, uint32_t& r2, uint32_t& r3, uint32_t a) {
    asm volatile("ldmatrix.sync.aligned.m8n8.x4.shared.b16 {%0,%1,%2,%3},[%4];"
                 : "=r"(r0), "=r"(r1), "=r"(r2), "=r"(r3) : "r"(a));
}
// f16-accumulate mma: C/D = 2 regs (f16x2); reg0 = row gid, reg1 = row gid+8
__device__ __forceinline__ void mma16816_h(uint32_t* c, const uint32_t* a, const uint32_t* b) {
    asm volatile("mma.sync.aligned.m16n8k16.row.col.f16.f16.f16.f16 "
                 "{%0,%1},{%2,%3,%4,%5},{%6,%7},{%0,%1};"
                 : "+r"(c[0]), "+r"(c[1])
                 : "r"(a[0]), "r"(a[1]), "r"(a[2]), "r"(a[3]), "r"(b[0]), "r"(b[1]));
}
__device__ __forceinline__ void cp16(uint32_t s, const void* g) {
    asm volatile("cp.async.cg.shared.global [%0],[%1],16;\n" :: "r"(s), "l"(g) : "memory");
}
#define CP_COMMIT() asm volatile("cp.async.commit_group;\n" ::: "memory")
#define CP_WAIT_N(n) asm volatile("cp.async.wait_group %0;\n" :: "n"(n) : "memory")

// Shared GEMM geometry: block 128M x 128N, 128 threads (4 warps, 2M x 2N),
// warp 64x64, BK=64, 2 stages, f16 accumulators.
// Row stride 144B (conflict-free). smem 72KB, ~150 regs -> 3 blocks/SM.
#define BK 64
#define T_STG 18432          // 128 rows * 144 B
#define GA_OFF(st) ((st)*T_STG)
#define GB_OFF(st) (2*T_STG + (st)*T_STG)
#define SMEM_G (4*T_STG)     // 73728

#define N13 ((size_t)NEXP*2*HID*DIM)

// ---------------- weight conversion (fp32 -> fp16) ----------------
__global__ void k_conv(const float* __restrict__ w13, const float* __restrict__ w2) {
    size_t i = ((size_t)blockIdx.x * 256 + threadIdx.x) * 4;
    if (i < N13) {
        float4 v = *reinterpret_cast<const float4*>(w13 + i);
        *reinterpret_cast<__half2*>(g_w13h + i)     = __floats2half2_rn(v.x, v.y);
        *reinterpret_cast<__half2*>(g_w13h + i + 2) = __floats2half2_rn(v.z, v.w);
    } else {
        size_t j = i - N13;
        float4 v = *reinterpret_cast<const float4*>(w2 + j);
        *reinterpret_cast<__half2*>(g_w2h + j)     = __floats2half2_rn(v.x, v.y);
        *reinterpret_cast<__half2*>(g_w2h + j + 2) = __floats2half2_rn(v.z, v.w);
    }
}

// ---------------- router (+ fused per-chunk expert count) ----------------
__global__ void k_router(const float* __restrict__ x, const float* __restrict__ gw) {
    __shared__ int se[16];
    const int warp = threadIdx.x >> 5, lane = threadIdx.x & 31;
    const int t = blockIdx.x * 8 + warp;
    float acc[NEXP];
    #pragma unroll
    for (int e = 0; e < NEXP; e++) acc[e] = 0.f;
    const float* xr = x + (size_t)t * DIM;
    for (int i = lane; i < DIM; i += 32) {
        float xv = xr[i];
        #pragma unroll
        for (int e = 0; e < NEXP; e++) acc[e] += xv * gw[e * DIM + i];
    }
    #pragma unroll
    for (int e = 0; e < NEXP; e++) {
        #pragma unroll
        for (int off = 16; off; off >>= 1)
            acc[e] += __shfl_xor_sync(0xffffffffu, acc[e], off);
    }
    if (lane == 0) {
        int e1 = 0; float l1 = acc[0];
        #pragma unroll
        for (int e = 1; e < NEXP; e++) if (acc[e] > l1) { l1 = acc[e]; e1 = e; }
        int e2 = (e1 == 0) ? 1 : 0; float l2 = acc[e2];
        #pragma unroll
        for (int e = 0; e < NEXP; e++)
            if (e != e1 && acc[e] > l2) { l2 = acc[e]; e2 = e; }
        float w1 = 1.f / (1.f + expf(l2 - l1));
        g_pair_expert[2 * t]     = e1;
        g_pair_expert[2 * t + 1] = e2;
        g_pair_weight[2 * t]     = w1;
        g_pair_weight[2 * t + 1] = 1.f - w1;
        se[2 * warp]     = e1;
        se[2 * warp + 1] = e2;
    }
    __syncthreads();
    if (threadIdx.x < NEXP) {
        int cnt = 0;
        #pragma unroll
        for (int i = 0; i < 16; i++) cnt += (se[i] == (int)threadIdx.x);
        g_ch_cnt[blockIdx.x][threadIdx.x] = cnt;
    }
}

// ---------------- dispatch: scan / scatter ----------------
__global__ __launch_bounds__(1024) void k_scan() {
    __shared__ int s[1024][NEXP];
    const int t = threadIdx.x;
    int a[NEXP], b[NEXP], tot[NEXP];
    #pragma unroll
    for (int e = 0; e < NEXP; e++) {
        a[e] = g_ch_cnt[2 * t][e];
        b[e] = g_ch_cnt[2 * t + 1][e];
        tot[e] = a[e] + b[e];
        s[t][e] = tot[e];
    }
    __syncthreads();
    for (int off = 1; off < 1024; off <<= 1) {
        int v[NEXP];
        #pragma unroll
        for (int e = 0; e < NEXP; e++)
            v[e] = s[t][e] + ((t >= off) ? s[t - off][e] : 0);
        __syncthreads();
        #pragma unroll
        for (int e = 0; e < NEXP; e++) s[t][e] = v[e];
        __syncthreads();
    }
    #pragma unroll
    for (int e = 0; e < NEXP; e++) {
        int excl = s[t][e] - tot[e];
        g_ch_base[2 * t][e] = excl;
        g_ch_base[2 * t + 1][e] = excl + a[e];
    }
    if (t < NEXP) g_count[t] = min(s[1023][t], CAP);
}

__global__ void k_scatter() {
    int c = blockIdx.x * 64 + threadIdx.x;
    int base[NEXP];
    #pragma unroll
    for (int e = 0; e < NEXP; e++) base[e] = g_ch_base[c][e];
    const int4* ep = reinterpret_cast<const int4*>(g_pair_expert + c * 16);
    #pragma unroll
    for (int i = 0; i < 4; i++) {
        int4 v = ep[i];
        int es[4] = {v.x, v.y, v.z, v.w};
        #pragma unroll
        for (int q = 0; q < 4; q++) {
            int p = c * 16 + i * 4 + q;
            int eq = es[q];
            int pos = 0;
            #pragma unroll
            for (int e = 0; e < NEXP; e++)
                if (eq == e) { pos = base[e]; base[e] = pos + 1; }
            if (pos < CAP) {
                int slot = eq * CAP + pos;
                g_pair_slot[p] = slot;
                g_slot_token[slot] = p >> 1;
            } else {
                g_pair_slot[p] = -1;
            }
        }
    }
}

// ---------------- zbuf: RMSNorm(2x)*norm_w -> fp16 (192 threads, float4) ----------------
__global__ void k_zbuf(const float* __restrict__ x, const float* __restrict__ nw) {
    const int slot = blockIdx.x;
    const int e = slot / CAP;
    const int tid = threadIdx.x;
    __half* zr = g_zbuf + (size_t)slot * DIM;
    const int local = slot - e * CAP;
    const int cnt = g_count[e];
    if (local >= cnt) {
        if (local < ((cnt + 127) & ~127))
            reinterpret_cast<uint2*>(zr)[tid] = make_uint2(0u, 0u);
        return;
    }
    const int t = g_slot_token[slot];
    float4 v = reinterpret_cast<const float4*>(x + (size_t)t * DIM)[tid];
    float ss = v.x * v.x + v.y * v.y + v.z * v.z + v.w * v.w;
    #pragma unroll
    for (int off = 16; off; off >>= 1) ss += __shfl_xor_sync(0xffffffffu, ss, off);
    __shared__ float red[6];
    if ((tid & 31) == 0) red[tid >> 5] = ss;
    __syncthreads();
    float tot = 0.f;
    #pragma unroll
    for (int w = 0; w < 6; w++) tot += red[w];
    float scale = rsqrtf(4.f * tot / (float)DIM + 1e-6f) * 2.f;
    float4 w4 = reinterpret_cast<const float4*>(nw + (size_t)e * DIM)[tid];
    __half2 h0 = __floats2half2_rn(v.x * scale * w4.x, v.y * scale * w4.y);
    __half2 h1 = __floats2half2_rn(v.z * scale * w4.z, v.w * scale * w4.w);
    uint2 o;
    o.x = *reinterpret_cast<uint32_t*>(&h0);
    o.y = *reinterpret_cast<uint32_t*>(&h1);
    reinterpret_cast<uint2*>(zr)[tid] = o;
}

// ---------------- GEMM1: 128M x (64g+64u), 4 warps 64x64, BK=64, f16 acc, 2 stages ----------------
__global__ __launch_bounds__(128, 3) void k_gemm1() {
    extern __shared__ char smem[];
    const int e = blockIdx.z;
    const int row0 = blockIdx.y * 128;
    if (row0 >= g_count[e]) return;
    const int jb = blockIdx.x * 64;
    const uint32_t sb = smem_u32(smem);
    const int tid = threadIdx.x, lane = tid & 31, wid = tid >> 5;
    const int wm = wid & 1, wn = wid >> 1;
    const int m0 = wm * 64;

    const __half* Ag  = g_zbuf + (size_t)(e * CAP + row0) * DIM;
    const __half* Bgg = g_w13h + (size_t)e * (2 * HID) * DIM + (size_t)jb * DIM;
    const __half* Bgu = g_w13h + (size_t)e * (2 * HID) * DIM + (size_t)(HID + jb) * DIM;

    uint32_t hacc[4][8][2];
    #pragma unroll
    for (int i = 0; i < 4; i++)
        #pragma unroll
        for (int j = 0; j < 8; j++) { hacc[i][j][0] = 0u; hacc[i][j][1] = 0u; }

    auto load_tile = [&](int st, int kt) {
        const int k0 = kt * BK;
        #pragma unroll
        for (int i = 0; i < 8; i++) {
            int id = tid + i * 128;
            int row = id >> 3, c16 = id & 7;
            cp16(sb + GA_OFF(st) + row * 144 + c16 * 16, Ag + (size_t)row * DIM + k0 + c16 * 8);
            const __half* bs = (row < 64) ? (Bgg + (size_t)row * DIM)
                                          : (Bgu + (size_t)(row - 64) * DIM);
            cp16(sb + GB_OFF(st) + row * 144 + c16 * 16, bs + k0 + c16 * 8);
        }
        CP_COMMIT();
    };

    const int KT = DIM / BK;                       // 12
    load_tile(0, 0);

    #pragma unroll 1
    for (int kt = 0; kt < KT; kt++) {
        CP_WAIT_N(0);
        __syncthreads();
        if (kt + 1 < KT) load_tile((kt + 1) & 1, kt + 1);
        const int st = kt & 1;
        #pragma unroll
        for (int ka = 0; ka < 4; ka++) {
            uint32_t af[4][4];
            #pragma unroll
            for (int i = 0; i < 4; i++) {
                uint32_t addr = sb + GA_OFF(st) + (m0 + i * 16 + (lane & 15)) * 144
                              + ka * 32 + ((lane >> 4) << 4);
                ldsm_x4(af[i][0], af[i][1], af[i][2], af[i][3], addr);
            }
            uint32_t bf[8][2];
            #pragma unroll
            for (int jp = 0; jp < 4; jp++) {
                int j0 = jp * 2;
                int m = lane >> 3;
                int jj = j0 + (m >> 1);
                int brow = (jj < 4) ? (wn * 32 + jj * 8) : (64 + wn * 32 + (jj - 4) * 8);
                uint32_t addr = sb + GB_OFF(st) + (brow + (lane & 7)) * 144
                              + ka * 32 + ((m & 1) << 4);
                uint32_t r0, r1, r2, r3;
                ldsm_x4(r0, r1, r2, r3, addr);
                bf[j0][0] = r0; bf[j0][1] = r1;
                bf[j0 + 1][0] = r2; bf[j0 + 1][1] = r3;
            }
            #pragma unroll
            for (int i = 0; i < 4; i++)
                #pragma unroll
                for (int j = 0; j < 8; j++)
                    mma16816_h(hacc[i][j], af[i], bf[j]);
        }
        __syncthreads();
    }

    // epilogue: h = silu(g)*u ; j<4 g cols, j>=4 u, same h cols
    const int gid = lane >> 2, qid = lane & 3;
    __half* Hb = g_hbuf + (size_t)(e * CAP + row0) * HID + jb;
    #pragma unroll
    for (int i = 0; i < 4; i++) {
        #pragma unroll
        for (int j = 0; j < 4; j++) {
            int hc = wn * 32 + j * 8 + qid * 2;
            #pragma unroll
            for (int half = 0; half < 2; half++) {
                int r = m0 + i * 16 + gid + half * 8;
                float2 gg = __half22float2(*reinterpret_cast<__half2*>(&hacc[i][j][half]));
                float2 uu = __half22float2(*reinterpret_cast<__half2*>(&hacc[i][j + 4][half]));
                float h0 = gg.x * uu.x / (1.f + __expf(-gg.x));
                float h1 = gg.y * uu.y / (1.f + __expf(-gg.y));
                *reinterpret_cast<__half2*>(Hb + (size_t)r * HID + hc) =
                    __floats2half2_rn(h0, h1);
            }
        }
    }
}

// ---------------- GEMM2: 128M x 128N, 4 warps 64x64, BK=64, f16 acc, 2 stages ----------------
__global__ __launch_bounds__(128, 3) void k_gemm2() {
    extern __shared__ char smem[];
    const int e = blockIdx.z;
    const int row0 = blockIdx.y * 128;
    if (row0 >= g_count[e]) return;
    const int db = blockIdx.x * 128;
    const uint32_t sb = smem_u32(smem);
    const int tid = threadIdx.x, lane = tid & 31, wid = tid >> 5;
    const int wm = wid & 1, wn = wid >> 1;
    const int m0 = wm * 64;

    const __half* Ag = g_hbuf + (size_t)(e * CAP + row0) * HID;
    const __half* Bg = g_w2h + (size_t)e * DIM * HID + (size_t)db * HID;

    uint32_t hacc[4][8][2];
    #pragma unroll
    for (int i = 0; i < 4; i++)
        #pragma unroll
        for (int j = 0; j < 8; j++) { hacc[i][j][0] = 0u; hacc[i][j][1] = 0u; }

    auto load_tile = [&](int st, int kt) {
        const int k0 = kt * BK;
        #pragma unroll
        for (int i = 0; i < 8; i++) {
            int id = tid + i * 128;
            int row = id >> 3, c16 = id & 7;
            cp16(sb + GA_OFF(st) + row * 144 + c16 * 16, Ag + (size_t)row * HID + k0 + c16 * 8);
            cp16(sb + GB_OFF(st) + row * 144 + c16 * 16, Bg + (size_t)row * HID + k0 + c16 * 8);
        }
        CP_COMMIT();
    };

    const int KT = HID / BK;                       // 32
    load_tile(0, 0);

    #pragma unroll 1
    for (int kt = 0; kt < KT; kt++) {
        CP_WAIT_N(0);
        __syncthreads();
        if (kt + 1 < KT) load_tile((kt + 1) & 1, kt + 1);
        const int st = kt & 1;
        #pragma unroll
        for (int ka = 0; ka < 4; ka++) {
            uint32_t af[4][4];
            #pragma unroll
            for (int i = 0; i < 4; i++) {
                uint32_t addr = sb + GA_OFF(st) + (m0 + i * 16 + (lane & 15)) * 144
                              + ka * 32 + ((lane >> 4) << 4);
                ldsm_x4(af[i][0], af[i][1], af[i][2], af[i][3], addr);
            }
            uint32_t bf[8][2];
            #pragma unroll
            for (int jp = 0; jp < 4; jp++) {
                int j0 = jp * 2;
                int m = lane >> 3;
                int jj = j0 + (m >> 1);
                int brow = wn * 64 + jj * 8;
                uint32_t addr = sb + GB_OFF(st) + (brow + (lane & 7)) * 144
                              + ka * 32 + ((m & 1) << 4);
                uint32_t r0, r1, r2, r3;
                ldsm_x4(r0, r1, r2, r3, addr);
                bf[j0][0] = r0; bf[j0][1] = r1;
                bf[j0 + 1][0] = r2; bf[j0 + 1][1] = r3;
            }
            #pragma unroll
            for (int i = 0; i < 4; i++)
                #pragma unroll
                for (int j = 0; j < 8; j++)
                    mma16816_h(hacc[i][j], af[i], bf[j]);
        }
        __syncthreads();
    }

    const int gid = lane >> 2, qid = lane & 3;
    __half* Yb = g_ybuf + (size_t)(e * CAP + row0) * DIM + db;
    #pragma unroll
    for (int i = 0; i < 4; i++) {
        #pragma unroll
        for (int j = 0; j < 8; j++) {
            int dc = wn * 64 + j * 8 + qid * 2;
            #pragma unroll
            for (int half = 0; half < 2; half++) {
                int r = m0 + i * 16 + gid + half * 8;
                *reinterpret_cast<__half2*>(Yb + (size_t)r * DIM + dc) =
                    *reinterpret_cast<__half2*>(&hacc[i][j][half]);
            }
        }
    }
}

// ---------------- combine (192 threads, float4 x / half2 y) ----------------
__global__ void k_combine(const float* __restrict__ x, float* __restrict__ out) {
    const int t = blockIdx.x, tid = threadIdx.x;
    int s0 = g_pair_slot[2 * t], s1 = g_pair_slot[2 * t + 1];
    float w0 = g_pair_weight[2 * t], w1 = g_pair_weight[2 * t + 1];
    if (s0 < 0) w0 = 0.f;
    if (s1 < 0) w1 = 0.f;
    const float wsum = w0 + w1;
    float4 xv = reinterpret_cast<const float4*>(x + (size_t)t * DIM)[tid];
    float4 a;
    a.x = wsum * xv.x; a.y = wsum * xv.y; a.z = wsum * xv.z; a.w = wsum * xv.w;
    if (s0 >= 0) {
        uint2 yp = reinterpret_cast<const uint2*>(g_ybuf + (size_t)s0 * DIM)[tid];
        float2 lo = __half22float2(*reinterpret_cast<__half2*>(&yp.x));
        float2 hi = __half22float2(*reinterpret_cast<__half2*>(&yp.y));
        a.x += w0 * lo.x; a.y += w0 * lo.y; a.z += w0 * hi.x; a.w += w0 * hi.y;
    }
    if (s1 >= 0) {
        uint2 yp = reinterpret_cast<const uint2*>(g_ybuf + (size_t)s1 * DIM)[tid];
        float2 lo = __half22float2(*reinterpret_cast<__half2*>(&yp.x));
        float2 hi = __half22float2(*reinterpret_cast<__half2*>(&yp.y));
        a.x += w1 * lo.x; a.y += w1 * lo.y; a.z += w1 * hi.x; a.w += w1 * hi.y;
    }
    reinterpret_cast<float4*>(out + (size_t)t * DIM)[tid] = a;
}

// ---------------- launch ----------------
extern "C" void kernel_launch(void* const* d_in, const int* in_sizes, int n_in,
                              void* d_out, int out_size) {
    const float* x      = (const float*)d_in[0];
    const float* gate_w = (const float*)d_in[1];
    const float* w13    = (const float*)d_in[2];
    const float* w2     = (const float*)d_in[3];
    const float* norm_w = (const float*)d_in[4];
    float* out = (float*)d_out;

    cudaFuncSetAttribute(k_gemm1, cudaFuncAttributeMaxDynamicSharedMemorySize, SMEM_G);
    cudaFuncSetAttribute(k_gemm2, cudaFuncAttributeMaxDynamicSharedMemorySize, SMEM_G);

    const int conv_blocks = (int)((N13 + (size_t)NEXP * DIM * HID) / 1024);
    k_conv<<<conv_blocks, 256>>>(w13, w2);
    k_router<<<NCH, 256>>>(x, gate_w);
    k_scan<<<1, 1024>>>();
    k_scatter<<<32, 64>>>();
    k_zbuf<<<ECAP, 192>>>(x, norm_w);
    k_gemm1<<<dim3(HID / 64, CAP / 128, NEXP), 128, SMEM_G>>>();
    k_gemm2<<<dim3(DIM / 128, CAP / 128, NEXP), 128, SMEM_G>>>();
    k_combine<<<N_TOK, 192>>>(x, out);
}